// round 17
// baseline (speedup 1.0000x reference)
#include <cuda_runtime.h>
#include <cuda_fp16.h>
#include <math.h>

#define NP 16384
#define NR 8192

typedef unsigned long long ull;

// ============================ scratch buffers ============================
__device__ __align__(16) __half g_xcatH[(size_t)NP * 384];
__device__ __align__(16) __half g_xcatL[(size_t)NP * 384];
__device__ __align__(16) __half g_h1H  [(size_t)NP * 384];
__device__ __align__(16) __half g_h1L  [(size_t)NP * 384];
__device__ __align__(16) __half g_buf2H[(size_t)NP * 256];   // cols 0-127 cc2, 128-255 maxfeat
__device__ __align__(16) __half g_buf2L[(size_t)NP * 256];
__device__ __align__(16) __half g_co1H [(size_t)NP * 256];
__device__ __align__(16) __half g_co1L [(size_t)NP * 256];
__device__ __align__(16) __half g_fullH[(size_t)NP * 160];   // cols 0-31 pcd, 32-159 attach
__device__ __align__(16) __half g_fullL[(size_t)NP * 160];
__device__ __align__(16) __half g_d1H  [(size_t)NP * 160];
__device__ __align__(16) __half g_d1L  [(size_t)NP * 160];
__device__ __align__(16) __half g_d2H  [(size_t)NP * 160];
__device__ __align__(16) __half g_d2L  [(size_t)NP * 160];
__device__ __align__(16) __half g_fpH  [(size_t)NP * 128];
__device__ __align__(16) __half g_fpL  [(size_t)NP * 128];
__device__ __align__(16) __half g_rgbTH[(size_t)NR * 128];
__device__ __align__(16) __half g_rgbTL[(size_t)NR * 128];
__device__ int g_idx[NP * 3];
#define WTOT 397312
__device__ __align__(16) __half g_whi[WTOT];
__device__ __align__(16) __half g_wlo[WTOT];

// ============================ helpers ============================
__device__ __forceinline__ void splitf(float x, __half& h, __half& l) {
    h = __float2half(x);
    l = __float2half(x - __half2float(h));
}
__device__ __forceinline__ void mma16816(float* d, const unsigned* a, const unsigned* b) {
    asm volatile("mma.sync.aligned.m16n8k16.row.col.f32.f16.f16.f32 "
        "{%0,%1,%2,%3}, {%4,%5,%6,%7}, {%8,%9}, {%0,%1,%2,%3};"
        : "+f"(d[0]), "+f"(d[1]), "+f"(d[2]), "+f"(d[3])
        : "r"(a[0]), "r"(a[1]), "r"(a[2]), "r"(a[3]), "r"(b[0]), "r"(b[1]));
}
__device__ __forceinline__ void ldm4(unsigned* r, unsigned addr) {
    asm volatile("ldmatrix.sync.aligned.m8n8.x4.shared.b16 {%0,%1,%2,%3}, [%4];"
        : "=r"(r[0]), "=r"(r[1]), "=r"(r[2]), "=r"(r[3]) : "r"(addr));
}
__device__ __forceinline__ void cpa16(unsigned dst, const void* src) {
    asm volatile("cp.async.cg.shared.global [%0], [%1], 16;" :: "r"(dst), "l"(src));
}
__device__ __forceinline__ void cpa_commit() {
    asm volatile("cp.async.commit_group;" ::: "memory");
}
__device__ __forceinline__ void cpa_wait0() {
    asm volatile("cp.async.wait_group 0;" ::: "memory");
}

// ============================ fused prep + knn ============================
// blocks [0,256): 3-NN (scheduled first, overlaps with light prep blocks)
// blocks [256, 256+PREP_BLKS): weight fp32 -> fp16 hi/lo
// next 1024: rgb transpose+split ; next 512: pcd transpose+split
#define PREP_BLKS ((WTOT + 255) / 256)
#define KNN_BLKS 256
__global__ __launch_bounds__(256) void prep_knn(
    const float* __restrict__ cc1, const float* __restrict__ cc2,
    const float* __restrict__ co1, const float* __restrict__ co2,
    const float* __restrict__ dh1, const float* __restrict__ dh2,
    const float* __restrict__ dh3, const float* __restrict__ sh1,
    __half* __restrict__ dhi, __half* __restrict__ dlo,
    const float* __restrict__ rgbf,
    __half* __restrict__ rgbTH, __half* __restrict__ rgbTL,
    const float* __restrict__ pcdf,
    __half* __restrict__ fullH, __half* __restrict__ fullL,
    const float* __restrict__ pcd, const float* __restrict__ rgb,
    int* __restrict__ outIdx)
{
    __shared__ __align__(16) char sbuf[38912];
    int bid = blockIdx.x;
    int tid = threadIdx.x;

    if (bid < KNN_BLKS) {
        // ---- 3-NN: 4 threads/point, 64 points/block ----
        float4* srgb = (float4*)sbuf;                      // 2048 * 16 B
        float*  md   = (float*)(sbuf + 32768);             // 256*3
        int*    mi   = (int*)  (sbuf + 32768 + 3072);      // 256*3
        int pl = tid & 63;
        int q  = tid >> 6;
        int p  = bid * 64 + pl;
        float px = pcd[p * 3 + 0], py = pcd[p * 3 + 1], pz = pcd[p * 3 + 2];
        float b0 = 1e30f, b1 = 1e30f, b2 = 1e30f;
        int i0 = 0, i1 = 0, i2 = 0;
        for (int t = 0; t < NR; t += 2048) {
            __syncthreads();
            for (int e = tid; e < 2048; e += 256) {
                int j = t + e;
                srgb[e] = make_float4(rgb[j * 3 + 0], rgb[j * 3 + 1], rgb[j * 3 + 2], 0.f);
            }
            __syncthreads();
            #pragma unroll 8
            for (int i = 0; i < 512; i++) {
                int e = (i << 2) | q;
                float4 rr = srgb[e];
                float dx = px - rr.x, dy = py - rr.y, dz = pz - rr.z;
                float d2 = dx * dx; d2 = fmaf(dy, dy, d2); d2 = fmaf(dz, dz, d2);
                if (d2 < b2) {
                    int idx = t + e;
                    if (d2 < b0)      { b2 = b1; i2 = i1; b1 = b0; i1 = i0; b0 = d2; i0 = idx; }
                    else if (d2 < b1) { b2 = b1; i2 = i1; b1 = d2; i1 = idx; }
                    else              { b2 = d2; i2 = idx; }
                }
            }
        }
        md[tid * 3 + 0] = b0; md[tid * 3 + 1] = b1; md[tid * 3 + 2] = b2;
        mi[tid * 3 + 0] = i0; mi[tid * 3 + 1] = i1; mi[tid * 3 + 2] = i2;
        __syncthreads();
        if (tid < 64) {
            int ptr[4] = {0, 0, 0, 0};
            #pragma unroll
            for (int t3 = 0; t3 < 3; t3++) {
                float best = 3.4e38f; int bq = 0, bidx = 0x7fffffff;
                #pragma unroll
                for (int qq = 0; qq < 4; qq++) {
                    if (ptr[qq] < 3) {
                        int rr = (qq * 64 + tid) * 3 + ptr[qq];
                        float d = md[rr]; int ix = mi[rr];
                        if (d < best || (d == best && ix < bidx)) { best = d; bq = qq; bidx = ix; }
                    }
                }
                ptr[bq]++;
                outIdx[p * 3 + t3] = (sqrtf(best) > 0.075f) ? -1 : bidx;
            }
        }
    } else if (bid < KNN_BLKS + PREP_BLKS) {
        int g = (bid - KNN_BLKS) * 256 + tid;
        if (g >= WTOT) return;
        const float* src; int loc, K, Kpad;
        if      (g < 147456) { src = cc1; loc = g;          K = 384; Kpad = 384; }
        else if (g < 196608) { src = cc2; loc = g - 147456; K = 384; Kpad = 384; }
        else if (g < 262144) { src = co1; loc = g - 196608; K = 256; Kpad = 256; }
        else if (g < 294912) { src = co2; loc = g - 262144; K = 256; Kpad = 256; }
        else if (g < 325632) { src = dh1; loc = g - 294912; K = 160; Kpad = 192; }
        else if (g < 356352) { src = dh2; loc = g - 325632; K = 160; Kpad = 192; }
        else if (g < 380928) { src = dh3; loc = g - 356352; K = 160; Kpad = 192; }
        else                 { src = sh1; loc = g - 380928; K = 128; Kpad = 128; }
        int r = loc / Kpad, c = loc - r * Kpad;
        float x = (c < K) ? src[r * K + c] : 0.f;
        __half h, l; splitf(x, h, l);
        dhi[g] = h; dlo[g] = l;
    } else if (bid < KNN_BLKS + PREP_BLKS + 1024) {
        float (*tile)[33] = (float(*)[33])sbuf;
        int tx = tid & 31, ty = tid >> 5;
        int b2 = bid - KNN_BLKS - PREP_BLKS;
        int c0 = (b2 >> 8) * 32;
        int n0 = (b2 & 255) * 32;
        #pragma unroll
        for (int i = 0; i < 32; i += 8)
            tile[ty + i][tx] = rgbf[(c0 + ty + i) * NR + n0 + tx];
        __syncthreads();
        #pragma unroll
        for (int i = 0; i < 32; i += 8) {
            float v = tile[tx][ty + i];
            __half h, l; splitf(v, h, l);
            size_t o = (size_t)(n0 + ty + i) * 128 + c0 + tx;
            rgbTH[o] = h; rgbTL[o] = l;
        }
    } else {
        float (*t)[33] = (float(*)[33])sbuf;
        int tx = tid & 31, ty = tid >> 5;
        int b3 = bid - KNN_BLKS - PREP_BLKS - 1024;
        int n0 = b3 * 32;
        #pragma unroll
        for (int i = 0; i < 32; i += 8) t[ty + i][tx] = pcdf[(ty + i) * NP + n0 + tx];
        __syncthreads();
        #pragma unroll
        for (int i = 0; i < 32; i += 8) {
            float v = t[tx][ty + i];
            __half h, l; splitf(v, h, l);
            size_t o = (size_t)(n0 + ty + i) * 160 + tx;
            fullH[o] = h; fullL[o] = l;
        }
    }
}

// ============================ fused gather + maxfeat ============================
__global__ __launch_bounds__(256) void gather_max(
    const __half* __restrict__ rgbTH, const __half* __restrict__ rgbTL,
    const int* __restrict__ idx,
    __half* __restrict__ xcatH, __half* __restrict__ xcatL,
    __half* __restrict__ buf2H, __half* __restrict__ buf2L)
{
    int e = blockIdx.x * 256 + threadIdx.x;
    int c4 = e & 31;
    int p = e >> 5;
    float m[4] = {-1e30f, -1e30f, -1e30f, -1e30f};
    #pragma unroll
    for (int j = 0; j < 3; j++) {
        int row = idx[p * 3 + j];
        uint2 vh = make_uint2(0u, 0u), vl = make_uint2(0u, 0u);
        if (row >= 0) {
            vh = *(const uint2*)(rgbTH + (size_t)row * 128 + c4 * 4);
            vl = *(const uint2*)(rgbTL + (size_t)row * 128 + c4 * 4);
        }
        size_t o = (size_t)p * 384 + j * 128 + c4 * 4;
        *(uint2*)(xcatH + o) = vh;
        *(uint2*)(xcatL + o) = vl;
        __half2 h01 = *(__half2*)&vh.x, h23 = *(__half2*)&vh.y;
        __half2 l01 = *(__half2*)&vl.x, l23 = *(__half2*)&vl.y;
        m[0] = fmaxf(m[0], __low2float(h01)  + __low2float(l01));
        m[1] = fmaxf(m[1], __high2float(h01) + __high2float(l01));
        m[2] = fmaxf(m[2], __low2float(h23)  + __low2float(l23));
        m[3] = fmaxf(m[3], __high2float(h23) + __high2float(l23));
    }
    __half hh[4], ll[4];
    #pragma unroll
    for (int q = 0; q < 4; q++) splitf(m[q], hh[q], ll[q]);
    size_t o = (size_t)p * 256 + 128 + c4 * 4;
    *(__half2*)(buf2H + o)     = __halves2half2(hh[0], hh[1]);
    *(__half2*)(buf2H + o + 2) = __halves2half2(hh[2], hh[3]);
    *(__half2*)(buf2L + o)     = __halves2half2(ll[0], ll[1]);
    *(__half2*)(buf2L + o + 2) = __halves2half2(ll[2], ll[3]);
}

// ============================ HMMA GEMM (128x128, cp.async, ldmatrix, fp32 acc) ============================
// fuse: 0 = plain; 1 = L2-normalize rows -> outV (grid.y must be 1); 2 = score -> outS (grid.y 1)
#define LDW 40
#define PLANE (128 * LDW)
#define STG   (4 * PLANE)
#define AH 0
#define AL PLANE
#define BH (2 * PLANE)
#define BL (3 * PLANE)
__global__ __launch_bounds__(256, 2) void gemm_hmma(
    const __half* __restrict__ Xh, const __half* __restrict__ Xl, int pitchA, int K,
    const __half* __restrict__ Whi, const __half* __restrict__ Wlo, int Wpitch, int Cout,
    __half* __restrict__ Yh, __half* __restrict__ Yl, int pitchY,
    const float* __restrict__ bias, const float* __restrict__ bn, int mode,
    int fuse, const float* __restrict__ w2, const float* __restrict__ b2,
    float* __restrict__ outS, float* __restrict__ outV)
{
    extern __shared__ __half sdyn[];
    __shared__ float sSc[128], sSh[128], sW2[128];
    __shared__ float sPart[128][8];
    __shared__ float sInv[128];

    const int tid = threadIdx.x;
    const int lane = tid & 31, wid = tid >> 5;
    const int wm = wid >> 1, wn = wid & 1;
    const int g = lane >> 2, tc = lane & 3;
    const int n0 = blockIdx.x * 128;
    const int nb0 = blockIdx.y * 128;
    const int NT = min(128, Cout - nb0);

    if (tid < 128) {
        float sc = 0.f, sh = 0.f;
        if (tid < NT) {
            int m = nb0 + tid;
            float b = bias[m];
            sc = 1.f; sh = b;
            if (mode) {
                float gg = bn[m], be = bn[Cout + m], mn = bn[2 * Cout + m], v = bn[3 * Cout + m];
                float inv = gg * rsqrtf(v + 1e-5f);
                sc = inv; sh = (b - mn) * inv + be;
            }
        }
        sSc[tid] = sc; sSh[tid] = sh;
        sW2[tid] = (fuse == 2) ? w2[tid] : 0.f;
    }

    float acc[2][8][4];
    #pragma unroll
    for (int a = 0; a < 2; a++)
        #pragma unroll
        for (int b = 0; b < 8; b++)
            #pragma unroll
            for (int c = 0; c < 4; c++) acc[a][b][c] = 0.f;

    const int r0c = tid >> 2,         o0c = (tid & 3) * 8;
    const int r1c = (tid + 256) >> 2, o1c = ((tid + 256) & 3) * 8;
    const unsigned sbase = (unsigned)__cvta_generic_to_shared(sdyn);

    const int slabs = K >> 5;

    #define LOAD_SLAB(sl) do {                                                      \
        int k0_ = (sl) << 5;                                                        \
        unsigned sb_ = sbase + ((sl) & 1) * (STG * 2);                              \
        cpa16(sb_ + (AH + r0c * LDW + o0c) * 2, Xh + (size_t)(n0 + r0c) * pitchA + k0_ + o0c);  \
        cpa16(sb_ + (AH + r1c * LDW + o1c) * 2, Xh + (size_t)(n0 + r1c) * pitchA + k0_ + o1c);  \
        cpa16(sb_ + (AL + r0c * LDW + o0c) * 2, Xl + (size_t)(n0 + r0c) * pitchA + k0_ + o0c);  \
        cpa16(sb_ + (AL + r1c * LDW + o1c) * 2, Xl + (size_t)(n0 + r1c) * pitchA + k0_ + o1c);  \
        cpa16(sb_ + (BH + r0c * LDW + o0c) * 2, Whi + (size_t)(nb0 + r0c) * Wpitch + k0_ + o0c); \
        cpa16(sb_ + (BH + r1c * LDW + o1c) * 2, Whi + (size_t)(nb0 + r1c) * Wpitch + k0_ + o1c); \
        cpa16(sb_ + (BL + r0c * LDW + o0c) * 2, Wlo + (size_t)(nb0 + r0c) * Wpitch + k0_ + o0c); \
        cpa16(sb_ + (BL + r1c * LDW + o1c) * 2, Wlo + (size_t)(nb0 + r1c) * Wpitch + k0_ + o1c); \
        cpa_commit();                                                               \
    } while (0)

    const int arow = wm * 32 + (lane & 15);
    const int akk0 = (lane >> 4) * 8;
    const int brow = wn * 64 + ((lane >> 4) << 3) + (lane & 7);
    const int bkk0 = ((lane >> 3) & 1) * 8;

    LOAD_SLAB(0);
    for (int sl = 0; sl < slabs; sl++) {
        cpa_wait0();
        __syncthreads();
        if (sl + 1 < slabs) LOAD_SLAB(sl + 1);

        const unsigned stb = sbase + (sl & 1) * (STG * 2);
        #pragma unroll
        for (int s = 0; s < 2; s++) {
            const int akk = s * 16 + akk0;
            const int bkk = s * 16 + bkk0;
            unsigned ah[2][4], al[2][4];
            #pragma unroll
            for (int mt = 0; mt < 2; mt++) {
                unsigned off = ((arow + mt * 16) * LDW + akk) * 2;
                ldm4(ah[mt], stb + (AH * 2) + off);
                ldm4(al[mt], stb + (AL * 2) + off);
            }
            #pragma unroll
            for (int jp = 0; jp < 4; jp++) {
                unsigned boff = ((brow + jp * 16) * LDW + bkk) * 2;
                unsigned bh[4], bl[4];
                ldm4(bh, stb + (BH * 2) + boff);
                ldm4(bl, stb + (BL * 2) + boff);
                #pragma unroll
                for (int h = 0; h < 2; h++) {
                    int nt = jp * 2 + h;
                    #pragma unroll
                    for (int mt = 0; mt < 2; mt++) {
                        mma16816(acc[mt][nt], ah[mt], bh + 2 * h);
                        mma16816(acc[mt][nt], al[mt], bh + 2 * h);
                        mma16816(acc[mt][nt], ah[mt], bl + 2 * h);
                    }
                }
            }
        }
        __syncthreads();
    }

    // --- epilogue: bias/BN/ReLU in-place ---
    #pragma unroll
    for (int mt = 0; mt < 2; mt++) {
        #pragma unroll
        for (int nt = 0; nt < 8; nt++) {
            int col = wn * 64 + nt * 8 + tc * 2;
            float* a = acc[mt][nt];
            if (col < NT) {
                float y0 = a[0] * sSc[col] + sSh[col];
                float y1 = a[1] * sSc[col + 1] + sSh[col + 1];
                float y2 = a[2] * sSc[col] + sSh[col];
                float y3 = a[3] * sSc[col + 1] + sSh[col + 1];
                if (mode) {
                    y0 = fmaxf(y0, 0.f); y1 = fmaxf(y1, 0.f);
                    y2 = fmaxf(y2, 0.f); y3 = fmaxf(y3, 0.f);
                }
                a[0] = y0; a[1] = y1; a[2] = y2; a[3] = y3;
            } else { a[0] = a[1] = a[2] = a[3] = 0.f; }
        }
    }

    if (fuse) {
        float red[2][2] = {{0.f, 0.f}, {0.f, 0.f}};
        #pragma unroll
        for (int mt = 0; mt < 2; mt++)
            #pragma unroll
            for (int nt = 0; nt < 8; nt++) {
                int col = wn * 64 + nt * 8 + tc * 2;
                float* a = acc[mt][nt];
                if (fuse == 1) {
                    red[mt][0] += a[0] * a[0] + a[1] * a[1];
                    red[mt][1] += a[2] * a[2] + a[3] * a[3];
                } else {
                    red[mt][0] += a[0] * sW2[col] + a[1] * sW2[col + 1];
                    red[mt][1] += a[2] * sW2[col] + a[3] * sW2[col + 1];
                }
            }
        int slot = wn * 4 + tc;
        #pragma unroll
        for (int mt = 0; mt < 2; mt++) {
            int rl = wm * 32 + mt * 16 + g;
            sPart[rl][slot]     = red[mt][0];
            sPart[rl + 8][slot] = red[mt][1];
        }
        __syncthreads();
        if (tid < 128) {
            float s = 0.f;
            #pragma unroll
            for (int q = 0; q < 8; q++) s += sPart[tid][q];
            if (fuse == 1) sInv[tid] = 1.f / fmaxf(sqrtf(s), 1e-12f);
            else           outS[n0 + tid] = 1.f / (1.f + expf(-(s + b2[0])));
        }
        __syncthreads();
    }

    if (fuse != 2) {
        #pragma unroll
        for (int mt = 0; mt < 2; mt++) {
            int rl = wm * 32 + mt * 16 + g;
            int r0 = n0 + rl;
            float inv0 = (fuse == 1) ? sInv[rl] : 0.f;
            float inv1 = (fuse == 1) ? sInv[rl + 8] : 0.f;
            #pragma unroll
            for (int nt = 0; nt < 8; nt++) {
                int col = wn * 64 + nt * 8 + tc * 2;
                if (col < NT) {
                    float* a = acc[mt][nt];
                    __half h0, l0, h1, l1, h2, l2, h3, l3;
                    splitf(a[0], h0, l0); splitf(a[1], h1, l1);
                    splitf(a[2], h2, l2); splitf(a[3], h3, l3);
                    *(__half2*)(Yh + (size_t)r0 * pitchY + nb0 + col)       = __halves2half2(h0, h1);
                    *(__half2*)(Yh + (size_t)(r0 + 8) * pitchY + nb0 + col) = __halves2half2(h2, h3);
                    *(__half2*)(Yl + (size_t)r0 * pitchY + nb0 + col)       = __halves2half2(l0, l1);
                    *(__half2*)(Yl + (size_t)(r0 + 8) * pitchY + nb0 + col) = __halves2half2(l2, l3);
                    if (fuse == 1) {
                        *(float2*)(outV + (size_t)r0 * 128 + col)       = make_float2(a[0] * inv0, a[1] * inv0);
                        *(float2*)(outV + (size_t)(r0 + 8) * 128 + col) = make_float2(a[2] * inv1, a[3] * inv1);
                    }
                }
            }
        }
    }
}

// ============================ launch ============================
extern "C" void kernel_launch(void* const* d_in, const int* in_sizes, int n_in,
                              void* d_out, int out_size)
{
    const float* pcd_xyz  = (const float*)d_in[0];
    const float* rgb_xyz  = (const float*)d_in[1];
    const float* pcd_feat = (const float*)d_in[2];
    const float* rgb_feat = (const float*)d_in[3];
    const float* cc1_w = (const float*)d_in[4];
    const float* cc1_b = (const float*)d_in[5];
    const float* cc_bn = (const float*)d_in[6];
    const float* cc2_w = (const float*)d_in[7];
    const float* cc2_b = (const float*)d_in[8];
    const float* co1_w = (const float*)d_in[9];
    const float* co1_b = (const float*)d_in[10];
    const float* co_bn = (const float*)d_in[11];
    const float* co2_w = (const float*)d_in[12];
    const float* co2_b = (const float*)d_in[13];
    const float* dh1_w = (const float*)d_in[14];
    const float* dh1_b = (const float*)d_in[15];
    const float* dh1_bn = (const float*)d_in[16];
    const float* dh2_w = (const float*)d_in[17];
    const float* dh2_b = (const float*)d_in[18];
    const float* dh2_bn = (const float*)d_in[19];
    const float* dh3_w = (const float*)d_in[20];
    const float* dh3_b = (const float*)d_in[21];
    const float* sh1_w = (const float*)d_in[22];
    const float* sh1_b = (const float*)d_in[23];
    const float* sh_bn = (const float*)d_in[24];
    const float* sh2_w = (const float*)d_in[25];
    const float* sh2_b = (const float*)d_in[26];

    __half *xcH, *xcL, *h1H, *h1L, *b2H, *b2L, *coH, *coL, *fuH, *fuL;
    __half *d1H, *d1L, *d2H, *d2L, *fpH, *fpL, *rgH, *rgL, *whi, *wlo;
    int* idx;
    cudaGetSymbolAddress((void**)&xcH, g_xcatH); cudaGetSymbolAddress((void**)&xcL, g_xcatL);
    cudaGetSymbolAddress((void**)&h1H, g_h1H);   cudaGetSymbolAddress((void**)&h1L, g_h1L);
    cudaGetSymbolAddress((void**)&b2H, g_buf2H); cudaGetSymbolAddress((void**)&b2L, g_buf2L);
    cudaGetSymbolAddress((void**)&coH, g_co1H);  cudaGetSymbolAddress((void**)&coL, g_co1L);
    cudaGetSymbolAddress((void**)&fuH, g_fullH); cudaGetSymbolAddress((void**)&fuL, g_fullL);
    cudaGetSymbolAddress((void**)&d1H, g_d1H);   cudaGetSymbolAddress((void**)&d1L, g_d1L);
    cudaGetSymbolAddress((void**)&d2H, g_d2H);   cudaGetSymbolAddress((void**)&d2L, g_d2L);
    cudaGetSymbolAddress((void**)&fpH, g_fpH);   cudaGetSymbolAddress((void**)&fpL, g_fpL);
    cudaGetSymbolAddress((void**)&rgH, g_rgbTH); cudaGetSymbolAddress((void**)&rgL, g_rgbTL);
    cudaGetSymbolAddress((void**)&whi, g_whi);   cudaGetSymbolAddress((void**)&wlo, g_wlo);
    cudaGetSymbolAddress((void**)&idx, g_idx);

    float* out = (float*)d_out;

    const int SMEM = 2 * STG * 2;   // 81920 bytes
    cudaFuncSetAttribute(gemm_hmma, cudaFuncAttributeMaxDynamicSharedMemorySize, SMEM);

    const int O_CC1 = 0,      O_CC2 = 147456, O_CO1 = 196608, O_CO2 = 262144;
    const int O_DH1 = 294912, O_DH2 = 325632, O_DH3 = 356352, O_SH1 = 380928;

    prep_knn<<<KNN_BLKS + PREP_BLKS + 1024 + 512, 256>>>(
        cc1_w, cc2_w, co1_w, co2_w, dh1_w, dh2_w, dh3_w, sh1_w, whi, wlo,
        rgb_feat, rgH, rgL, pcd_feat, fuH, fuL,
        pcd_xyz, rgb_xyz, idx);
    gather_max<<<NP * 32 / 256, 256>>>(rgH, rgL, idx, xcH, xcL, b2H, b2L);

    gemm_hmma<<<dim3(128, 3), 256, SMEM>>>(xcH, xcL, 384, 384, whi + O_CC1, wlo + O_CC1, 384, 384,
                                           h1H, h1L, 384, cc1_b, cc_bn, 1, 0, nullptr, nullptr, nullptr, nullptr);
    gemm_hmma<<<dim3(128, 1), 256, SMEM>>>(h1H, h1L, 384, 384, whi + O_CC2, wlo + O_CC2, 384, 128,
                                           b2H, b2L, 256, cc2_b, nullptr, 0, 0, nullptr, nullptr, nullptr, nullptr);
    gemm_hmma<<<dim3(128, 2), 256, SMEM>>>(b2H, b2L, 256, 256, whi + O_CO1, wlo + O_CO1, 256, 256,
                                           coH, coL, 256, co1_b, co_bn, 1, 0, nullptr, nullptr, nullptr, nullptr);
    gemm_hmma<<<dim3(128, 1), 256, SMEM>>>(coH, coL, 256, 256, whi + O_CO2, wlo + O_CO2, 256, 128,
                                           fuH + 32, fuL + 32, 160, co2_b, nullptr, 0, 0, nullptr, nullptr, nullptr, nullptr);
    gemm_hmma<<<dim3(128, 2), 256, SMEM>>>(fuH, fuL, 160, 160, whi + O_DH1, wlo + O_DH1, 192, 160,
                                           d1H, d1L, 160, dh1_b, dh1_bn, 1, 0, nullptr, nullptr, nullptr, nullptr);
    gemm_hmma<<<dim3(128, 2), 256, SMEM>>>(d1H, d1L, 160, 160, whi + O_DH2, wlo + O_DH2, 192, 160,
                                           d2H, d2L, 160, dh2_b, dh2_bn, 1, 0, nullptr, nullptr, nullptr, nullptr);
    // dh3: fuse=1 -> writes fp hi/lo planes AND L2-normalized vf directly
    gemm_hmma<<<dim3(128, 1), 256, SMEM>>>(d2H, d2L, 160, 160, whi + O_DH3, wlo + O_DH3, 192, 128,
                                           fpH, fpL, 128, dh3_b, nullptr, 0,
                                           1, nullptr, nullptr, nullptr, out + NP * 3 + NP);
    // sh1: fuse=2 -> computes vote scores directly (no activation output)
    gemm_hmma<<<dim3(128, 1), 256, SMEM>>>(fpH, fpL, 128, 128, whi + O_SH1, wlo + O_SH1, 128, 128,
                                           nullptr, nullptr, 0, sh1_b, sh_bn, 1,
                                           2, sh2_w, sh2_b, out + NP * 3, nullptr);

    cudaMemcpyAsync(out, pcd_xyz, NP * 3 * sizeof(float), cudaMemcpyDeviceToDevice, 0);
}